// round 3
// baseline (speedup 1.0000x reference)
#include <cuda_runtime.h>

#define NU 100000
#define NE 1600000
#define NB 16384
#define D  128

// ---- static scratch (no allocations allowed) ----
static __device__ int   g_rowptr[NU + 1];
static __device__ int   g_cursor[NU];
static __device__ int   g_esrc[NE];
static __device__ float g_h1[(size_t)NU * D];   // layer-1 user output

// ---------------- CSR build ----------------
__global__ void k_zero() {
    int i = blockIdx.x * blockDim.x + threadIdx.x;
    if (i < NU) g_cursor[i] = 0;
}

__global__ void k_count(const int* __restrict__ dst) {
    int e = blockIdx.x * blockDim.x + threadIdx.x;   // grid exact (NE % 256 == 0)
    atomicAdd(&g_cursor[dst[e]], 1);
}

__global__ void k_scan() {
    __shared__ int sh[1024];
    const int t  = threadIdx.x;
    const int CH = (NU + 1023) / 1024;   // 98
    int b0 = t * CH;
    int b1 = min(b0 + CH, NU);
    int sum = 0;
    for (int i = b0; i < b1; i++) sum += g_cursor[i];
    int val = sum;
    sh[t] = val;
    __syncthreads();
    for (int off = 1; off < 1024; off <<= 1) {
        int tmp = (t >= off) ? sh[t - off] : 0;
        __syncthreads();
        val += tmp;
        sh[t] = val;
        __syncthreads();
    }
    int base = val - sum;   // exclusive prefix
    for (int i = b0; i < b1; i++) {
        int c = g_cursor[i];
        g_rowptr[i] = base;
        g_cursor[i] = base;   // running cursor for scatter
        base += c;
    }
    if (t == 1023) g_rowptr[NU] = base;   // == NE
}

__global__ void k_scatter(const int* __restrict__ src, const int* __restrict__ dst) {
    int e = blockIdx.x * blockDim.x + threadIdx.x;
    int p = atomicAdd(&g_cursor[dst[e]], 1);
    g_esrc[p] = src[e];
}

// ---------------- helpers ----------------
__device__ __forceinline__ float f4e(const float4 v, int i) {
    return (i == 0) ? v.x : (i == 1) ? v.y : (i == 2) ? v.z : v.w;
}

// per-warp neighbor mean of one row into smem (lane owns float4 slot)
__device__ __forceinline__ void warp_agg_row(
    const float* __restrict__ table, int node, int lane, float* dst128)
{
    int beg = g_rowptr[node], end = g_rowptr[node + 1];
    float4 a = make_float4(0.f, 0.f, 0.f, 0.f);
    int e = beg;
    for (; e + 2 <= end; e += 2) {
        int s0 = g_esrc[e], s1 = g_esrc[e + 1];
        float4 x0 = ((const float4*)(table + (size_t)s0 * D))[lane];
        float4 x1 = ((const float4*)(table + (size_t)s1 * D))[lane];
        a.x += x0.x + x1.x; a.y += x0.y + x1.y;
        a.z += x0.z + x1.z; a.w += x0.w + x1.w;
    }
    if (e < end) {
        int s = g_esrc[e];
        float4 x = ((const float4*)(table + (size_t)s * D))[lane];
        a.x += x.x; a.y += x.y; a.z += x.z; a.w += x.w;
    }
    float inv = 1.f / fmaxf((float)(end - beg), 1.f);
    a.x *= inv; a.y *= inv; a.z *= inv; a.w *= inv;
    ((float4*)dst128)[lane] = a;
}

// ---------------- fused SAGE layer 1 (all users) ----------------
// block = 256 thr (8 warps), 32 rows/block, 4 rows/warp, 4 cols/lane
__global__ __launch_bounds__(256, 1) void k_fused1(
    const float* __restrict__ feat, const float* __restrict__ Ws,
    const float* __restrict__ Wn, const float* __restrict__ bias)
{
    extern __shared__ float sm[];
    float* sWs = sm;                    // 16384
    float* sWn = sm + 16384;            // 16384
    float* sB  = sm + 32768;            // 128
    float* sX  = sm + 32896;            // 32*128
    float* sH  = sm + 32896 + 32 * D;   // 32*128
    const int tid = threadIdx.x;
    {
        const float4* g0 = (const float4*)Ws;
        const float4* g1 = (const float4*)Wn;
        float4* s0 = (float4*)sWs;
        float4* s1 = (float4*)sWn;
        for (int i = tid; i < 4096; i += 256) { s0[i] = g0[i]; s1[i] = g1[i]; }
        if (tid < 32) ((float4*)sB)[tid] = ((const float4*)bias)[tid];
    }
    const int warp = tid >> 5, lane = tid & 31;
    const int r0 = blockIdx.x * 32;      // NU % 32 == 0
#pragma unroll
    for (int j = 0; j < 4; j++) {
        int lr = warp * 4 + j;
        int row = r0 + lr;
        ((float4*)(sX + lr * D))[lane] = ((const float4*)(feat + (size_t)row * D))[lane];
        warp_agg_row(feat, row, lane, sH + lr * D);
    }
    __syncthreads();

    float acc[4][4];
#pragma unroll
    for (int j = 0; j < 4; j++)
#pragma unroll
        for (int c = 0; c < 4; c++) acc[j][c] = 0.f;

    for (int k4 = 0; k4 < D; k4 += 4) {
        float4 xv[4], hv[4];
#pragma unroll
        for (int j = 0; j < 4; j++) {
            xv[j] = *(const float4*)(sX + (warp * 4 + j) * D + k4);
            hv[j] = *(const float4*)(sH + (warp * 4 + j) * D + k4);
        }
#pragma unroll
        for (int kk = 0; kk < 4; kk++) {
            float4 ws = ((const float4*)(sWs + (k4 + kk) * D))[lane];
            float4 wn = ((const float4*)(sWn + (k4 + kk) * D))[lane];
#pragma unroll
            for (int j = 0; j < 4; j++) {
                float x = f4e(xv[j], kk), h = f4e(hv[j], kk);
                acc[j][0] += x * ws.x; acc[j][0] += h * wn.x;
                acc[j][1] += x * ws.y; acc[j][1] += h * wn.y;
                acc[j][2] += x * ws.z; acc[j][2] += h * wn.z;
                acc[j][3] += x * ws.w; acc[j][3] += h * wn.w;
            }
        }
    }

    float4 b4 = ((const float4*)sB)[lane];
    float v[4][4], ss[4];
#pragma unroll
    for (int j = 0; j < 4; j++) {
        float t0 = acc[j][0] + b4.x, t1 = acc[j][1] + b4.y;
        float t2 = acc[j][2] + b4.z, t3 = acc[j][3] + b4.w;
        t0 = t0 > 0.f ? t0 : 0.2f * t0;
        t1 = t1 > 0.f ? t1 : 0.2f * t1;
        t2 = t2 > 0.f ? t2 : 0.2f * t2;
        t3 = t3 > 0.f ? t3 : 0.2f * t3;
        v[j][0] = t0; v[j][1] = t1; v[j][2] = t2; v[j][3] = t3;
        ss[j] = t0 * t0 + t1 * t1 + t2 * t2 + t3 * t3;
    }
#pragma unroll
    for (int off = 16; off; off >>= 1) {
        ss[0] += __shfl_xor_sync(0xffffffffu, ss[0], off);
        ss[1] += __shfl_xor_sync(0xffffffffu, ss[1], off);
        ss[2] += __shfl_xor_sync(0xffffffffu, ss[2], off);
        ss[3] += __shfl_xor_sync(0xffffffffu, ss[3], off);
    }
#pragma unroll
    for (int j = 0; j < 4; j++) {
        float sc = 1.f / fmaxf(sqrtf(ss[j]), 1e-12f);
        int row = r0 + warp * 4 + j;
        ((float4*)(g_h1 + (size_t)row * D))[lane] =
            make_float4(v[j][0] * sc, v[j][1] * sc, v[j][2] * sc, v[j][3] * sc);
    }
}

// ---------------- fused SAGE layer 2 (selected users only) ----------------
__global__ __launch_bounds__(256, 1) void k_fused2(
    const float* __restrict__ ufeat, const int* __restrict__ users,
    const float* __restrict__ Ws, const float* __restrict__ Wn,
    const float* __restrict__ bias, float* __restrict__ out)
{
    extern __shared__ float sm[];
    float* sWs = sm;
    float* sWn = sm + 16384;
    float* sB  = sm + 32768;
    float* sX  = sm + 32896;
    float* sH  = sm + 32896 + 32 * D;
    const int tid = threadIdx.x;
    {
        const float4* g0 = (const float4*)Ws;
        const float4* g1 = (const float4*)Wn;
        float4* s0 = (float4*)sWs;
        float4* s1 = (float4*)sWn;
        for (int i = tid; i < 4096; i += 256) { s0[i] = g0[i]; s1[i] = g1[i]; }
        if (tid < 32) ((float4*)sB)[tid] = ((const float4*)bias)[tid];
    }
    const int warp = tid >> 5, lane = tid & 31;
    const int r0 = blockIdx.x * 32;      // NB % 32 == 0
#pragma unroll
    for (int j = 0; j < 4; j++) {
        int lr = warp * 4 + j;
        int b = r0 + lr;
        int u = users[b];
        float4 x4 = ((const float4*)(g_h1 + (size_t)u * D))[lane];
        ((float4*)(sX + lr * D))[lane] = x4;
        ((float4*)(out + (size_t)b * 384))[lane]       = ((const float4*)(ufeat + (size_t)u * D))[lane];
        ((float4*)(out + (size_t)b * 384 + 128))[lane] = x4;
        warp_agg_row(g_h1, u, lane, sH + lr * D);
    }
    __syncthreads();

    float acc[4][4];
#pragma unroll
    for (int j = 0; j < 4; j++)
#pragma unroll
        for (int c = 0; c < 4; c++) acc[j][c] = 0.f;

    for (int k4 = 0; k4 < D; k4 += 4) {
        float4 xv[4], hv[4];
#pragma unroll
        for (int j = 0; j < 4; j++) {
            xv[j] = *(const float4*)(sX + (warp * 4 + j) * D + k4);
            hv[j] = *(const float4*)(sH + (warp * 4 + j) * D + k4);
        }
#pragma unroll
        for (int kk = 0; kk < 4; kk++) {
            float4 ws = ((const float4*)(sWs + (k4 + kk) * D))[lane];
            float4 wn = ((const float4*)(sWn + (k4 + kk) * D))[lane];
#pragma unroll
            for (int j = 0; j < 4; j++) {
                float x = f4e(xv[j], kk), h = f4e(hv[j], kk);
                acc[j][0] += x * ws.x; acc[j][0] += h * wn.x;
                acc[j][1] += x * ws.y; acc[j][1] += h * wn.y;
                acc[j][2] += x * ws.z; acc[j][2] += h * wn.z;
                acc[j][3] += x * ws.w; acc[j][3] += h * wn.w;
            }
        }
    }

    float4 b4 = ((const float4*)sB)[lane];
    float v[4][4], ss[4];
#pragma unroll
    for (int j = 0; j < 4; j++) {
        float t0 = acc[j][0] + b4.x, t1 = acc[j][1] + b4.y;
        float t2 = acc[j][2] + b4.z, t3 = acc[j][3] + b4.w;
        t0 = t0 > 0.f ? t0 : 0.2f * t0;
        t1 = t1 > 0.f ? t1 : 0.2f * t1;
        t2 = t2 > 0.f ? t2 : 0.2f * t2;
        t3 = t3 > 0.f ? t3 : 0.2f * t3;
        v[j][0] = t0; v[j][1] = t1; v[j][2] = t2; v[j][3] = t3;
        ss[j] = t0 * t0 + t1 * t1 + t2 * t2 + t3 * t3;
    }
#pragma unroll
    for (int off = 16; off; off >>= 1) {
        ss[0] += __shfl_xor_sync(0xffffffffu, ss[0], off);
        ss[1] += __shfl_xor_sync(0xffffffffu, ss[1], off);
        ss[2] += __shfl_xor_sync(0xffffffffu, ss[2], off);
        ss[3] += __shfl_xor_sync(0xffffffffu, ss[3], off);
    }
#pragma unroll
    for (int j = 0; j < 4; j++) {
        float sc = 1.f / fmaxf(sqrtf(ss[j]), 1e-12f);
        int b = r0 + warp * 4 + j;
        ((float4*)(out + (size_t)b * 384 + 256))[lane] =
            make_float4(v[j][0] * sc, v[j][1] * sc, v[j][2] * sc, v[j][3] * sc);
    }
}

// ---------------- item tower (gathered rows only) ----------------
__global__ __launch_bounds__(256, 1) void k_items(
    const float* __restrict__ ifeat, const int* __restrict__ pos, const int* __restrict__ neg,
    const float* __restrict__ W0, const float* __restrict__ b0,
    const float* __restrict__ W1, const float* __restrict__ b1,
    float* __restrict__ out)
{
    extern __shared__ float sm[];
    float* sW0 = sm;            // 16384
    float* sW1 = sm + 16384;    // 16384
    float* sB0 = sm + 32768;    // 128
    float* sB1 = sm + 32896;    // 128
    float* sX  = sm + 33024;    // 32*128
    const int tid = threadIdx.x;
    {
        const float4* g0 = (const float4*)W0;
        const float4* g1 = (const float4*)W1;
        float4* s0 = (float4*)sW0;
        float4* s1 = (float4*)sW1;
        for (int i = tid; i < 4096; i += 256) { s0[i] = g0[i]; s1[i] = g1[i]; }
        if (tid < 32) {
            ((float4*)sB0)[tid] = ((const float4*)b0)[tid];
            ((float4*)sB1)[tid] = ((const float4*)b1)[tid];
        }
    }
    const int warp = tid >> 5, lane = tid & 31;
    const int r0 = blockIdx.x * 32;     // 2*NB % 32 == 0
#pragma unroll
    for (int j = 0; j < 4; j++) {
        int rr = r0 + warp * 4 + j;
        int idx = (rr < NB) ? pos[rr] : neg[rr - NB];
        float4 x4 = ((const float4*)(ifeat + (size_t)idx * D))[lane];
        ((float4*)(sX + (warp * 4 + j) * D))[lane] = x4;
        ((float4*)(out + (size_t)(NB + rr) * 384))[lane] = x4;   // raw feat segment
    }
    __syncthreads();

    // ---- layer 1 ----
    float acc[4][4];
#pragma unroll
    for (int j = 0; j < 4; j++)
#pragma unroll
        for (int c = 0; c < 4; c++) acc[j][c] = 0.f;

    for (int k4 = 0; k4 < D; k4 += 4) {
        float4 xv[4];
#pragma unroll
        for (int j = 0; j < 4; j++)
            xv[j] = *(const float4*)(sX + (warp * 4 + j) * D + k4);
#pragma unroll
        for (int kk = 0; kk < 4; kk++) {
            float4 w = ((const float4*)(sW0 + (k4 + kk) * D))[lane];
#pragma unroll
            for (int j = 0; j < 4; j++) {
                float x = f4e(xv[j], kk);
                acc[j][0] += x * w.x;
                acc[j][1] += x * w.y;
                acc[j][2] += x * w.z;
                acc[j][3] += x * w.w;
            }
        }
    }
    {
        float4 b4 = ((const float4*)sB0)[lane];
        float v[4][4], ss[4];
#pragma unroll
        for (int j = 0; j < 4; j++) {
            float t0 = acc[j][0] + b4.x, t1 = acc[j][1] + b4.y;
            float t2 = acc[j][2] + b4.z, t3 = acc[j][3] + b4.w;
            t0 = t0 > 0.f ? t0 : 0.2f * t0;
            t1 = t1 > 0.f ? t1 : 0.2f * t1;
            t2 = t2 > 0.f ? t2 : 0.2f * t2;
            t3 = t3 > 0.f ? t3 : 0.2f * t3;
            v[j][0] = t0; v[j][1] = t1; v[j][2] = t2; v[j][3] = t3;
            ss[j] = t0 * t0 + t1 * t1 + t2 * t2 + t3 * t3;
        }
#pragma unroll
        for (int off = 16; off; off >>= 1) {
            ss[0] += __shfl_xor_sync(0xffffffffu, ss[0], off);
            ss[1] += __shfl_xor_sync(0xffffffffu, ss[1], off);
            ss[2] += __shfl_xor_sync(0xffffffffu, ss[2], off);
            ss[3] += __shfl_xor_sync(0xffffffffu, ss[3], off);
        }
        __syncwarp();   // all lanes done reading sX before overwrite
#pragma unroll
        for (int j = 0; j < 4; j++) {
            float sc = 1.f / fmaxf(sqrtf(ss[j]), 1e-12f);
            float4 o = make_float4(v[j][0] * sc, v[j][1] * sc, v[j][2] * sc, v[j][3] * sc);
            int rr = r0 + warp * 4 + j;
            ((float4*)(sX + (warp * 4 + j) * D))[lane] = o;    // h1 becomes layer-2 input
            ((float4*)(out + (size_t)(NB + rr) * 384 + 128))[lane] = o;
        }
        __syncwarp();
    }

    // ---- layer 2 ----
#pragma unroll
    for (int j = 0; j < 4; j++)
#pragma unroll
        for (int c = 0; c < 4; c++) acc[j][c] = 0.f;

    for (int k4 = 0; k4 < D; k4 += 4) {
        float4 xv[4];
#pragma unroll
        for (int j = 0; j < 4; j++)
            xv[j] = *(const float4*)(sX + (warp * 4 + j) * D + k4);
#pragma unroll
        for (int kk = 0; kk < 4; kk++) {
            float4 w = ((const float4*)(sW1 + (k4 + kk) * D))[lane];
#pragma unroll
            for (int j = 0; j < 4; j++) {
                float x = f4e(xv[j], kk);
                acc[j][0] += x * w.x;
                acc[j][1] += x * w.y;
                acc[j][2] += x * w.z;
                acc[j][3] += x * w.w;
            }
        }
    }
    {
        float4 b4 = ((const float4*)sB1)[lane];
        float v[4][4], ss[4];
#pragma unroll
        for (int j = 0; j < 4; j++) {
            float t0 = acc[j][0] + b4.x, t1 = acc[j][1] + b4.y;
            float t2 = acc[j][2] + b4.z, t3 = acc[j][3] + b4.w;
            t0 = t0 > 0.f ? t0 : 0.2f * t0;
            t1 = t1 > 0.f ? t1 : 0.2f * t1;
            t2 = t2 > 0.f ? t2 : 0.2f * t2;
            t3 = t3 > 0.f ? t3 : 0.2f * t3;
            v[j][0] = t0; v[j][1] = t1; v[j][2] = t2; v[j][3] = t3;
            ss[j] = t0 * t0 + t1 * t1 + t2 * t2 + t3 * t3;
        }
#pragma unroll
        for (int off = 16; off; off >>= 1) {
            ss[0] += __shfl_xor_sync(0xffffffffu, ss[0], off);
            ss[1] += __shfl_xor_sync(0xffffffffu, ss[1], off);
            ss[2] += __shfl_xor_sync(0xffffffffu, ss[2], off);
            ss[3] += __shfl_xor_sync(0xffffffffu, ss[3], off);
        }
#pragma unroll
        for (int j = 0; j < 4; j++) {
            float sc = 1.f / fmaxf(sqrtf(ss[j]), 1e-12f);
            int rr = r0 + warp * 4 + j;
            ((float4*)(out + (size_t)(NB + rr) * 384 + 256))[lane] =
                make_float4(v[j][0] * sc, v[j][1] * sc, v[j][2] * sc, v[j][3] * sc);
        }
    }
}

// ---------------- launch ----------------
extern "C" void kernel_launch(void* const* d_in, const int* in_sizes, int n_in,
                              void* d_out, int out_size) {
    const int*   src   = (const int*)d_in[0];
    const int*   dst   = (const int*)d_in[1];
    const int*   users = (const int*)d_in[2];
    const int*   pos   = (const int*)d_in[3];
    const int*   neg   = (const int*)d_in[4];
    const float* ufeat = (const float*)d_in[5];
    const float* ifeat = (const float*)d_in[6];
    const float* Ws0   = (const float*)d_in[7];
    const float* Wn0   = (const float*)d_in[8];
    const float* bu0   = (const float*)d_in[9];
    const float* Wi0   = (const float*)d_in[10];
    const float* bi0   = (const float*)d_in[11];
    const float* Ws1   = (const float*)d_in[12];
    const float* Wn1   = (const float*)d_in[13];
    const float* bu1   = (const float*)d_in[14];
    const float* Wi1   = (const float*)d_in[15];
    const float* bi1   = (const float*)d_in[16];
    float* out = (float*)d_out;

    const int sm_dense = (16384 * 2 + 128 + 32 * D * 2) * sizeof(float);  // 163840+ B
    const int sm_items = (16384 * 2 + 256 + 32 * D) * sizeof(float);
    (void)cudaFuncSetAttribute(k_fused1, cudaFuncAttributeMaxDynamicSharedMemorySize, sm_dense);
    (void)cudaFuncSetAttribute(k_fused2, cudaFuncAttributeMaxDynamicSharedMemorySize, sm_dense);
    (void)cudaFuncSetAttribute(k_items,  cudaFuncAttributeMaxDynamicSharedMemorySize, sm_items);

    // CSR build
    k_zero   <<<(NU + 255) / 256, 256>>>();
    k_count  <<<NE / 256, 256>>>(dst);
    k_scan   <<<1, 1024>>>();
    k_scatter<<<NE / 256, 256>>>(src, dst);

    // user tower (agg fused into dense)
    k_fused1<<<NU / 32, 256, sm_dense>>>(ufeat, Ws0, Wn0, bu0);
    k_fused2<<<NB / 32, 256, sm_dense>>>(ufeat, users, Ws1, Wn1, bu1, out);

    // item tower (gathered rows only)
    k_items <<<(2 * NB) / 32, 256, sm_items>>>(ifeat, pos, neg, Wi0, bi0, Wi1, bi1, out);
}

// round 4
// speedup vs baseline: 1.1714x; 1.1714x over previous
#include <cuda_runtime.h>

#define NU 100000
#define NE 1600000
#define NB 16384
#define D  128

typedef unsigned long long u64;

// ---- static scratch (no allocations allowed) ----
static __device__ int   g_rowptr[NU + 1];
static __device__ int   g_cursor[NU];
static __device__ int   g_esrc[NE];
static __device__ float g_h1[(size_t)NU * D];   // layer-1 user output

// ---------------- packed f32x2 helpers ----------------
__device__ __forceinline__ u64 dup2(float x) {
    u64 r; asm("mov.b64 %0, {%1, %1};" : "=l"(r) : "f"(x)); return r;
}
__device__ __forceinline__ void ffma2(u64& d, u64 a, u64 b) {
    asm("fma.rn.f32x2 %0, %1, %2, %0;" : "+l"(d) : "l"(a), "l"(b));
}
__device__ __forceinline__ float2 unpk(u64 v) {
    float2 r; asm("mov.b64 {%0, %1}, %2;" : "=f"(r.x), "=f"(r.y) : "l"(v)); return r;
}

// ---------------- CSR build ----------------
__global__ void k_zero() {
    int i = blockIdx.x * blockDim.x + threadIdx.x;
    if (i < NU) g_cursor[i] = 0;
}

__global__ void k_count(const int* __restrict__ dst) {
    int i = blockIdx.x * blockDim.x + threadIdx.x;
    if (i < NE / 4) {
        int4 d = ((const int4*)dst)[i];
        atomicAdd(&g_cursor[d.x], 1);
        atomicAdd(&g_cursor[d.y], 1);
        atomicAdd(&g_cursor[d.z], 1);
        atomicAdd(&g_cursor[d.w], 1);
    }
}

__global__ void k_scan() {
    __shared__ int sh[1024];
    const int t  = threadIdx.x;
    const int CH = (NU + 1023) / 1024;   // 98
    int b0 = t * CH;
    int b1 = min(b0 + CH, NU);
    int sum = 0;
    for (int i = b0; i < b1; i++) sum += g_cursor[i];
    int val = sum;
    sh[t] = val;
    __syncthreads();
    for (int off = 1; off < 1024; off <<= 1) {
        int tmp = (t >= off) ? sh[t - off] : 0;
        __syncthreads();
        val += tmp;
        sh[t] = val;
        __syncthreads();
    }
    int base = val - sum;   // exclusive prefix
    for (int i = b0; i < b1; i++) {
        int c = g_cursor[i];
        g_rowptr[i] = base;
        g_cursor[i] = base;   // running cursor for scatter
        base += c;
    }
    if (t == 1023) g_rowptr[NU] = base;   // == NE
}

__global__ void k_scatter(const int* __restrict__ src, const int* __restrict__ dst) {
    int i = blockIdx.x * blockDim.x + threadIdx.x;
    if (i < NE / 4) {
        int4 d = ((const int4*)dst)[i];
        int4 s = ((const int4*)src)[i];
        int p0 = atomicAdd(&g_cursor[d.x], 1);
        int p1 = atomicAdd(&g_cursor[d.y], 1);
        int p2 = atomicAdd(&g_cursor[d.z], 1);
        int p3 = atomicAdd(&g_cursor[d.w], 1);
        g_esrc[p0] = s.x; g_esrc[p1] = s.y;
        g_esrc[p2] = s.z; g_esrc[p3] = s.w;
    }
}

// ---------------- per-warp neighbor mean (unroll x4) ----------------
__device__ __forceinline__ void warp_agg_row(
    const float* __restrict__ table, int node, int lane, float* dst128)
{
    int beg = g_rowptr[node], end = g_rowptr[node + 1];
    float4 a = make_float4(0.f, 0.f, 0.f, 0.f);
    int e = beg;
    for (; e + 4 <= end; e += 4) {
        int s0 = g_esrc[e],     s1 = g_esrc[e + 1];
        int s2 = g_esrc[e + 2], s3 = g_esrc[e + 3];
        float4 x0 = ((const float4*)(table + (size_t)s0 * D))[lane];
        float4 x1 = ((const float4*)(table + (size_t)s1 * D))[lane];
        float4 x2 = ((const float4*)(table + (size_t)s2 * D))[lane];
        float4 x3 = ((const float4*)(table + (size_t)s3 * D))[lane];
        a.x += (x0.x + x1.x) + (x2.x + x3.x);
        a.y += (x0.y + x1.y) + (x2.y + x3.y);
        a.z += (x0.z + x1.z) + (x2.z + x3.z);
        a.w += (x0.w + x1.w) + (x2.w + x3.w);
    }
    for (; e < end; e++) {
        int s = g_esrc[e];
        float4 x = ((const float4*)(table + (size_t)s * D))[lane];
        a.x += x.x; a.y += x.y; a.z += x.z; a.w += x.w;
    }
    float inv = 1.f / fmaxf((float)(end - beg), 1.f);
    a.x *= inv; a.y *= inv; a.z *= inv; a.w *= inv;
    ((float4*)dst128)[lane] = a;
}

// dual-matrix FFMA2 GEMM core: 8 rows/warp, 4 cols/lane (column pairs)
// acc0[j] = cols (c0,c1), acc1[j] = cols (c2,c3) for row lr0+j
__device__ __forceinline__ void gemm_dual8(
    const float* sX, const float* sH, const float* sWs, const float* sWn,
    int lr0, int lane, u64* acc0, u64* acc1)
{
#pragma unroll
    for (int j = 0; j < 8; j++) { acc0[j] = 0ull; acc1[j] = 0ull; }
#pragma unroll 4
    for (int k = 0; k < D; k += 2) {
        ulonglong2 wsa = *(const ulonglong2*)(sWs + k * D + lane * 4);
        ulonglong2 wsb = *(const ulonglong2*)(sWs + (k + 1) * D + lane * 4);
        ulonglong2 wna = *(const ulonglong2*)(sWn + k * D + lane * 4);
        ulonglong2 wnb = *(const ulonglong2*)(sWn + (k + 1) * D + lane * 4);
#pragma unroll
        for (int j = 0; j < 8; j++) {
            float2 x2 = *(const float2*)(sX + (lr0 + j) * D + k);
            float2 h2 = *(const float2*)(sH + (lr0 + j) * D + k);
            u64 xx0 = dup2(x2.x), xx1 = dup2(x2.y);
            u64 hh0 = dup2(h2.x), hh1 = dup2(h2.y);
            ffma2(acc0[j], xx0, wsa.x); ffma2(acc1[j], xx0, wsa.y);
            ffma2(acc0[j], hh0, wna.x); ffma2(acc1[j], hh0, wna.y);
            ffma2(acc0[j], xx1, wsb.x); ffma2(acc1[j], xx1, wsb.y);
            ffma2(acc0[j], hh1, wnb.x); ffma2(acc1[j], hh1, wnb.y);
        }
    }
}

// single-matrix FFMA2 GEMM core
__device__ __forceinline__ void gemm_one8(
    const float* sX, const float* sW, int lr0, int lane, u64* acc0, u64* acc1)
{
#pragma unroll
    for (int j = 0; j < 8; j++) { acc0[j] = 0ull; acc1[j] = 0ull; }
#pragma unroll 4
    for (int k = 0; k < D; k += 2) {
        ulonglong2 wa = *(const ulonglong2*)(sW + k * D + lane * 4);
        ulonglong2 wb = *(const ulonglong2*)(sW + (k + 1) * D + lane * 4);
#pragma unroll
        for (int j = 0; j < 8; j++) {
            float2 x2 = *(const float2*)(sX + (lr0 + j) * D + k);
            u64 xx0 = dup2(x2.x), xx1 = dup2(x2.y);
            ffma2(acc0[j], xx0, wa.x); ffma2(acc1[j], xx0, wa.y);
            ffma2(acc0[j], xx1, wb.x); ffma2(acc1[j], xx1, wb.y);
        }
    }
}

// epilogue: +bias, leaky-relu, return 4 values + per-row sumsq (pre-reduce)
__device__ __forceinline__ float epi4(u64 a0, u64 a1, float4 b4, float4& v) {
    float2 p01 = unpk(a0), p23 = unpk(a1);
    float t0 = p01.x + b4.x, t1 = p01.y + b4.y;
    float t2 = p23.x + b4.z, t3 = p23.y + b4.w;
    t0 = t0 > 0.f ? t0 : 0.2f * t0;
    t1 = t1 > 0.f ? t1 : 0.2f * t1;
    t2 = t2 > 0.f ? t2 : 0.2f * t2;
    t3 = t3 > 0.f ? t3 : 0.2f * t3;
    v = make_float4(t0, t1, t2, t3);
    return t0 * t0 + t1 * t1 + t2 * t2 + t3 * t3;
}

// ---------------- fused SAGE layer 1 (all users) ----------------
// 256 thr (8 warps), 64 rows/block, 8 rows/warp
__global__ __launch_bounds__(256, 1) void k_fused1(
    const float* __restrict__ feat, const float* __restrict__ Ws,
    const float* __restrict__ Wn, const float* __restrict__ bias)
{
    extern __shared__ float sm[];
    float* sWs = sm;                    // 16384
    float* sWn = sm + 16384;            // 16384
    float* sB  = sm + 32768;            // 128
    float* sX  = sm + 32896;            // 64*128
    float* sH  = sm + 32896 + 64 * D;   // 64*128
    const int tid = threadIdx.x;
    {
        const float4* g0 = (const float4*)Ws;
        const float4* g1 = (const float4*)Wn;
        float4* s0 = (float4*)sWs;
        float4* s1 = (float4*)sWn;
        for (int i = tid; i < 4096; i += 256) { s0[i] = g0[i]; s1[i] = g1[i]; }
        if (tid < 32) ((float4*)sB)[tid] = ((const float4*)bias)[tid];
    }
    const int warp = tid >> 5, lane = tid & 31;
    const int lr0 = warp * 8;
    const int r0 = blockIdx.x * 64;
#pragma unroll
    for (int j = 0; j < 8; j++) {
        int row = r0 + lr0 + j;
        if (row < NU) {
            ((float4*)(sX + (lr0 + j) * D))[lane] =
                ((const float4*)(feat + (size_t)row * D))[lane];
            warp_agg_row(feat, row, lane, sH + (lr0 + j) * D);
        } else {
            ((float4*)(sX + (lr0 + j) * D))[lane] = make_float4(0.f, 0.f, 0.f, 0.f);
            ((float4*)(sH + (lr0 + j) * D))[lane] = make_float4(0.f, 0.f, 0.f, 0.f);
        }
    }
    __syncthreads();

    u64 acc0[8], acc1[8];
    gemm_dual8(sX, sH, sWs, sWn, lr0, lane, acc0, acc1);

    float4 b4 = ((const float4*)sB)[lane];
    float4 v[8]; float ss[8];
#pragma unroll
    for (int j = 0; j < 8; j++) ss[j] = epi4(acc0[j], acc1[j], b4, v[j]);
#pragma unroll
    for (int off = 16; off; off >>= 1) {
#pragma unroll
        for (int j = 0; j < 8; j++) ss[j] += __shfl_xor_sync(0xffffffffu, ss[j], off);
    }
#pragma unroll
    for (int j = 0; j < 8; j++) {
        int row = r0 + lr0 + j;
        if (row < NU) {
            float sc = 1.f / fmaxf(sqrtf(ss[j]), 1e-12f);
            ((float4*)(g_h1 + (size_t)row * D))[lane] =
                make_float4(v[j].x * sc, v[j].y * sc, v[j].z * sc, v[j].w * sc);
        }
    }
}

// ---------------- fused SAGE layer 2 (selected users only) ----------------
__global__ __launch_bounds__(256, 1) void k_fused2(
    const float* __restrict__ ufeat, const int* __restrict__ users,
    const float* __restrict__ Ws, const float* __restrict__ Wn,
    const float* __restrict__ bias, float* __restrict__ out)
{
    extern __shared__ float sm[];
    float* sWs = sm;
    float* sWn = sm + 16384;
    float* sB  = sm + 32768;
    float* sX  = sm + 32896;
    float* sH  = sm + 32896 + 64 * D;
    const int tid = threadIdx.x;
    {
        const float4* g0 = (const float4*)Ws;
        const float4* g1 = (const float4*)Wn;
        float4* s0 = (float4*)sWs;
        float4* s1 = (float4*)sWn;
        for (int i = tid; i < 4096; i += 256) { s0[i] = g0[i]; s1[i] = g1[i]; }
        if (tid < 32) ((float4*)sB)[tid] = ((const float4*)bias)[tid];
    }
    const int warp = tid >> 5, lane = tid & 31;
    const int lr0 = warp * 8;
    const int r0 = blockIdx.x * 64;     // NB % 64 == 0
#pragma unroll
    for (int j = 0; j < 8; j++) {
        int b = r0 + lr0 + j;
        int u = users[b];
        float4 x4 = ((const float4*)(g_h1 + (size_t)u * D))[lane];
        ((float4*)(sX + (lr0 + j) * D))[lane] = x4;
        ((float4*)(out + (size_t)b * 384))[lane]       = ((const float4*)(ufeat + (size_t)u * D))[lane];
        ((float4*)(out + (size_t)b * 384 + 128))[lane] = x4;
        warp_agg_row(g_h1, u, lane, sH + (lr0 + j) * D);
    }
    __syncthreads();

    u64 acc0[8], acc1[8];
    gemm_dual8(sX, sH, sWs, sWn, lr0, lane, acc0, acc1);

    float4 b4 = ((const float4*)sB)[lane];
    float4 v[8]; float ss[8];
#pragma unroll
    for (int j = 0; j < 8; j++) ss[j] = epi4(acc0[j], acc1[j], b4, v[j]);
#pragma unroll
    for (int off = 16; off; off >>= 1) {
#pragma unroll
        for (int j = 0; j < 8; j++) ss[j] += __shfl_xor_sync(0xffffffffu, ss[j], off);
    }
#pragma unroll
    for (int j = 0; j < 8; j++) {
        float sc = 1.f / fmaxf(sqrtf(ss[j]), 1e-12f);
        int b = r0 + lr0 + j;
        ((float4*)(out + (size_t)b * 384 + 256))[lane] =
            make_float4(v[j].x * sc, v[j].y * sc, v[j].z * sc, v[j].w * sc);
    }
}

// ---------------- item tower (gathered rows only) ----------------
__global__ __launch_bounds__(256, 1) void k_items(
    const float* __restrict__ ifeat, const int* __restrict__ pos, const int* __restrict__ neg,
    const float* __restrict__ W0, const float* __restrict__ b0,
    const float* __restrict__ W1, const float* __restrict__ b1,
    float* __restrict__ out)
{
    extern __shared__ float sm[];
    float* sW0 = sm;            // 16384
    float* sW1 = sm + 16384;    // 16384
    float* sB0 = sm + 32768;    // 128
    float* sB1 = sm + 32896;    // 128
    float* sX  = sm + 33024;    // 64*128
    const int tid = threadIdx.x;
    {
        const float4* g0 = (const float4*)W0;
        const float4* g1 = (const float4*)W1;
        float4* s0 = (float4*)sW0;
        float4* s1 = (float4*)sW1;
        for (int i = tid; i < 4096; i += 256) { s0[i] = g0[i]; s1[i] = g1[i]; }
        if (tid < 32) {
            ((float4*)sB0)[tid] = ((const float4*)b0)[tid];
            ((float4*)sB1)[tid] = ((const float4*)b1)[tid];
        }
    }
    const int warp = tid >> 5, lane = tid & 31;
    const int lr0 = warp * 8;
    const int r0 = blockIdx.x * 64;     // 2*NB % 64 == 0
#pragma unroll
    for (int j = 0; j < 8; j++) {
        int rr = r0 + lr0 + j;
        int idx = (rr < NB) ? pos[rr] : neg[rr - NB];
        float4 x4 = ((const float4*)(ifeat + (size_t)idx * D))[lane];
        ((float4*)(sX + (lr0 + j) * D))[lane] = x4;
        ((float4*)(out + (size_t)(NB + rr) * 384))[lane] = x4;   // raw feat segment
    }
    __syncthreads();

    // ---- layer 1 ----
    u64 acc0[8], acc1[8];
    gemm_one8(sX, sW0, lr0, lane, acc0, acc1);
    {
        float4 b4 = ((const float4*)sB0)[lane];
        float4 v[8]; float ss[8];
#pragma unroll
        for (int j = 0; j < 8; j++) ss[j] = epi4(acc0[j], acc1[j], b4, v[j]);
#pragma unroll
        for (int off = 16; off; off >>= 1) {
#pragma unroll
            for (int j = 0; j < 8; j++) ss[j] += __shfl_xor_sync(0xffffffffu, ss[j], off);
        }
        __syncwarp();   // all lanes done reading sX before overwrite
#pragma unroll
        for (int j = 0; j < 8; j++) {
            float sc = 1.f / fmaxf(sqrtf(ss[j]), 1e-12f);
            float4 o = make_float4(v[j].x * sc, v[j].y * sc, v[j].z * sc, v[j].w * sc);
            int rr = r0 + lr0 + j;
            ((float4*)(sX + (lr0 + j) * D))[lane] = o;    // becomes layer-2 input
            ((float4*)(out + (size_t)(NB + rr) * 384 + 128))[lane] = o;
        }
        __syncwarp();
    }

    // ---- layer 2 ----
    gemm_one8(sX, sW1, lr0, lane, acc0, acc1);
    {
        float4 b4 = ((const float4*)sB1)[lane];
        float4 v[8]; float ss[8];
#pragma unroll
        for (int j = 0; j < 8; j++) ss[j] = epi4(acc0[j], acc1[j], b4, v[j]);
#pragma unroll
        for (int off = 16; off; off >>= 1) {
#pragma unroll
            for (int j = 0; j < 8; j++) ss[j] += __shfl_xor_sync(0xffffffffu, ss[j], off);
        }
#pragma unroll
        for (int j = 0; j < 8; j++) {
            float sc = 1.f / fmaxf(sqrtf(ss[j]), 1e-12f);
            int rr = r0 + lr0 + j;
            ((float4*)(out + (size_t)(NB + rr) * 384 + 256))[lane] =
                make_float4(v[j].x * sc, v[j].y * sc, v[j].z * sc, v[j].w * sc);
        }
    }
}

// ---------------- launch ----------------
extern "C" void kernel_launch(void* const* d_in, const int* in_sizes, int n_in,
                              void* d_out, int out_size) {
    const int*   src   = (const int*)d_in[0];
    const int*   dst   = (const int*)d_in[1];
    const int*   users = (const int*)d_in[2];
    const int*   pos   = (const int*)d_in[3];
    const int*   neg   = (const int*)d_in[4];
    const float* ufeat = (const float*)d_in[5];
    const float* ifeat = (const float*)d_in[6];
    const float* Ws0   = (const float*)d_in[7];
    const float* Wn0   = (const float*)d_in[8];
    const float* bu0   = (const float*)d_in[9];
    const float* Wi0   = (const float*)d_in[10];
    const float* bi0   = (const float*)d_in[11];
    const float* Ws1   = (const float*)d_in[12];
    const float* Wn1   = (const float*)d_in[13];
    const float* bu1   = (const float*)d_in[14];
    const float* Wi1   = (const float*)d_in[15];
    const float* bi1   = (const float*)d_in[16];
    float* out = (float*)d_out;

    const int sm_dense = (16384 * 2 + 128 + 64 * D * 2) * sizeof(float);  // 197120 B
    const int sm_items = (16384 * 2 + 256 + 64 * D) * sizeof(float);      // 165888 B
    (void)cudaFuncSetAttribute(k_fused1, cudaFuncAttributeMaxDynamicSharedMemorySize, sm_dense);
    (void)cudaFuncSetAttribute(k_fused2, cudaFuncAttributeMaxDynamicSharedMemorySize, sm_dense);
    (void)cudaFuncSetAttribute(k_items,  cudaFuncAttributeMaxDynamicSharedMemorySize, sm_items);

    // CSR build
    k_zero   <<<(NU + 255) / 256, 256>>>();
    k_count  <<<(NE / 4 + 255) / 256, 256>>>(dst);
    k_scan   <<<1, 1024>>>();
    k_scatter<<<(NE / 4 + 255) / 256, 256>>>(src, dst);

    // user tower (agg fused into dense, FFMA2 GEMM)
    k_fused1<<<(NU + 63) / 64, 256, sm_dense>>>(ufeat, Ws0, Wn0, bu0);
    k_fused2<<<NB / 64, 256, sm_dense>>>(ufeat, users, Ws1, Wn1, bu1, out);

    // item tower (gathered rows only)
    k_items <<<(2 * NB) / 64, 256, sm_items>>>(ifeat, pos, neg, Wi0, bi0, Wi1, bi1, out);
}

// round 5
// speedup vs baseline: 1.4087x; 1.2026x over previous
#include <cuda_runtime.h>

#define NU 100000
#define NE 1600000
#define NB 16384
#define D  128

typedef unsigned long long u64;

// ---- static scratch (no allocations allowed) ----
static __device__ int   g_rowptr[NU + 1];
static __device__ int   g_cursor[NU];
static __device__ int   g_esrc[NE];
static __device__ float g_h1 [(size_t)NU * D];   // layer-1 user output
static __device__ float g_hn [(size_t)NU * D];   // layer-1 neighbor mean
static __device__ float g_hn2[(size_t)NB * D];   // layer-2 neighbor mean

// ---------------- packed f32x2 helpers ----------------
__device__ __forceinline__ u64 dup2(float x) {
    u64 r; asm("mov.b64 %0, {%1, %1};" : "=l"(r) : "f"(x)); return r;
}
__device__ __forceinline__ void ffma2(u64& d, u64 a, u64 b) {
    asm("fma.rn.f32x2 %0, %1, %2, %0;" : "+l"(d) : "l"(a), "l"(b));
}
__device__ __forceinline__ float2 unpk(u64 v) {
    float2 r; asm("mov.b64 {%0, %1}, %2;" : "=f"(r.x), "=f"(r.y) : "l"(v)); return r;
}

// ---------------- CSR build ----------------
__global__ void k_zero() {
    int i = blockIdx.x * blockDim.x + threadIdx.x;
    if (i < NU) g_cursor[i] = 0;
}

__global__ void k_count(const int* __restrict__ dst) {
    int i = blockIdx.x * blockDim.x + threadIdx.x;   // NE/8 threads
    if (i < NE / 8) {
        int4 d0 = ((const int4*)dst)[2 * i];
        int4 d1 = ((const int4*)dst)[2 * i + 1];
        atomicAdd(&g_cursor[d0.x], 1); atomicAdd(&g_cursor[d0.y], 1);
        atomicAdd(&g_cursor[d0.z], 1); atomicAdd(&g_cursor[d0.w], 1);
        atomicAdd(&g_cursor[d1.x], 1); atomicAdd(&g_cursor[d1.y], 1);
        atomicAdd(&g_cursor[d1.z], 1); atomicAdd(&g_cursor[d1.w], 1);
    }
}

__global__ void k_scan() {
    __shared__ int sh[1024];
    const int t  = threadIdx.x;
    const int CH = (NU + 1023) / 1024;   // 98
    int b0 = t * CH;
    int b1 = min(b0 + CH, NU);
    int sum = 0;
    for (int i = b0; i < b1; i++) sum += g_cursor[i];
    int val = sum;
    sh[t] = val;
    __syncthreads();
    for (int off = 1; off < 1024; off <<= 1) {
        int tmp = (t >= off) ? sh[t - off] : 0;
        __syncthreads();
        val += tmp;
        sh[t] = val;
        __syncthreads();
    }
    int base = val - sum;   // exclusive prefix
    for (int i = b0; i < b1; i++) {
        int c = g_cursor[i];
        g_rowptr[i] = base;
        g_cursor[i] = base;   // running cursor for scatter
        base += c;
    }
    if (t == 1023) g_rowptr[NU] = base;   // == NE
}

__global__ void k_scatter(const int* __restrict__ src, const int* __restrict__ dst) {
    int i = blockIdx.x * blockDim.x + threadIdx.x;
    if (i < NE / 8) {
        int4 d0 = ((const int4*)dst)[2 * i];
        int4 d1 = ((const int4*)dst)[2 * i + 1];
        int4 s0 = ((const int4*)src)[2 * i];
        int4 s1 = ((const int4*)src)[2 * i + 1];
        int p0 = atomicAdd(&g_cursor[d0.x], 1);
        int p1 = atomicAdd(&g_cursor[d0.y], 1);
        int p2 = atomicAdd(&g_cursor[d0.z], 1);
        int p3 = atomicAdd(&g_cursor[d0.w], 1);
        int p4 = atomicAdd(&g_cursor[d1.x], 1);
        int p5 = atomicAdd(&g_cursor[d1.y], 1);
        int p6 = atomicAdd(&g_cursor[d1.z], 1);
        int p7 = atomicAdd(&g_cursor[d1.w], 1);
        g_esrc[p0] = s0.x; g_esrc[p1] = s0.y; g_esrc[p2] = s0.z; g_esrc[p3] = s0.w;
        g_esrc[p4] = s1.x; g_esrc[p5] = s1.y; g_esrc[p6] = s1.z; g_esrc[p7] = s1.w;
    }
}

// ---------------- high-occupancy neighbor-mean aggregation ----------------
// one warp per row; 32 edge indices loaded by ONE coalesced LDG, shfl-broadcast;
// feature gathers issued in chunks of 8 (MLP=8, no idx->feat serialization).
__device__ __forceinline__ void agg_row(
    const float* __restrict__ table, int row, int lane, float* __restrict__ dstv)
{
    int beg = g_rowptr[row], end = g_rowptr[row + 1];
    int deg = end - beg;
    float4 a = make_float4(0.f, 0.f, 0.f, 0.f);
    for (int base = 0; base < deg; base += 32) {
        int rem = deg - base;
        int n = rem < 32 ? rem : 32;
        int myi = (lane < n) ? g_esrc[beg + base + lane] : 0;
        int j = 0;
        for (; j + 8 <= n; j += 8) {
            int s0 = __shfl_sync(0xffffffffu, myi, j + 0);
            int s1 = __shfl_sync(0xffffffffu, myi, j + 1);
            int s2 = __shfl_sync(0xffffffffu, myi, j + 2);
            int s3 = __shfl_sync(0xffffffffu, myi, j + 3);
            int s4 = __shfl_sync(0xffffffffu, myi, j + 4);
            int s5 = __shfl_sync(0xffffffffu, myi, j + 5);
            int s6 = __shfl_sync(0xffffffffu, myi, j + 6);
            int s7 = __shfl_sync(0xffffffffu, myi, j + 7);
            float4 x0 = ((const float4*)(table + (size_t)s0 * D))[lane];
            float4 x1 = ((const float4*)(table + (size_t)s1 * D))[lane];
            float4 x2 = ((const float4*)(table + (size_t)s2 * D))[lane];
            float4 x3 = ((const float4*)(table + (size_t)s3 * D))[lane];
            float4 x4 = ((const float4*)(table + (size_t)s4 * D))[lane];
            float4 x5 = ((const float4*)(table + (size_t)s5 * D))[lane];
            float4 x6 = ((const float4*)(table + (size_t)s6 * D))[lane];
            float4 x7 = ((const float4*)(table + (size_t)s7 * D))[lane];
            a.x += ((x0.x + x1.x) + (x2.x + x3.x)) + ((x4.x + x5.x) + (x6.x + x7.x));
            a.y += ((x0.y + x1.y) + (x2.y + x3.y)) + ((x4.y + x5.y) + (x6.y + x7.y));
            a.z += ((x0.z + x1.z) + (x2.z + x3.z)) + ((x4.z + x5.z) + (x6.z + x7.z));
            a.w += ((x0.w + x1.w) + (x2.w + x3.w)) + ((x4.w + x5.w) + (x6.w + x7.w));
        }
        for (; j < n; j++) {
            int s = __shfl_sync(0xffffffffu, myi, j);
            float4 x = ((const float4*)(table + (size_t)s * D))[lane];
            a.x += x.x; a.y += x.y; a.z += x.z; a.w += x.w;
        }
    }
    float inv = 1.f / fmaxf((float)deg, 1.f);
    a.x *= inv; a.y *= inv; a.z *= inv; a.w *= inv;
    ((float4*)dstv)[lane] = a;
}

__global__ __launch_bounds__(256) void k_agg1(const float* __restrict__ feat) {
    int row  = (blockIdx.x * blockDim.x + threadIdx.x) >> 5;
    int lane = threadIdx.x & 31;
    if (row < NU) agg_row(feat, row, lane, g_hn + (size_t)row * D);
}

__global__ __launch_bounds__(256) void k_agg2(const int* __restrict__ users) {
    int b    = (blockIdx.x * blockDim.x + threadIdx.x) >> 5;
    int lane = threadIdx.x & 31;
    if (b < NB) agg_row(g_h1, users[b], lane, g_hn2 + (size_t)b * D);
}

// ---------------- FFMA2 GEMM cores ----------------
// dual-matrix: 8 rows/warp, 4 cols/lane (two packed col-pairs)
__device__ __forceinline__ void gemm_dual8(
    const float* sX, const float* sH, const float* sWs, const float* sWn,
    int lr0, int lane, u64* acc0, u64* acc1)
{
#pragma unroll
    for (int j = 0; j < 8; j++) { acc0[j] = 0ull; acc1[j] = 0ull; }
#pragma unroll 4
    for (int k = 0; k < D; k += 2) {
        ulonglong2 wsa = *(const ulonglong2*)(sWs + k * D + lane * 4);
        ulonglong2 wsb = *(const ulonglong2*)(sWs + (k + 1) * D + lane * 4);
        ulonglong2 wna = *(const ulonglong2*)(sWn + k * D + lane * 4);
        ulonglong2 wnb = *(const ulonglong2*)(sWn + (k + 1) * D + lane * 4);
#pragma unroll
        for (int j = 0; j < 8; j++) {
            float2 x2 = *(const float2*)(sX + (lr0 + j) * D + k);
            float2 h2 = *(const float2*)(sH + (lr0 + j) * D + k);
            u64 xx0 = dup2(x2.x), xx1 = dup2(x2.y);
            u64 hh0 = dup2(h2.x), hh1 = dup2(h2.y);
            ffma2(acc0[j], xx0, wsa.x); ffma2(acc1[j], xx0, wsa.y);
            ffma2(acc0[j], hh0, wna.x); ffma2(acc1[j], hh0, wna.y);
            ffma2(acc0[j], xx1, wsb.x); ffma2(acc1[j], xx1, wsb.y);
            ffma2(acc0[j], hh1, wnb.x); ffma2(acc1[j], hh1, wnb.y);
        }
    }
}

__device__ __forceinline__ void gemm_one8(
    const float* sX, const float* sW, int lr0, int lane, u64* acc0, u64* acc1)
{
#pragma unroll
    for (int j = 0; j < 8; j++) { acc0[j] = 0ull; acc1[j] = 0ull; }
#pragma unroll 4
    for (int k = 0; k < D; k += 2) {
        ulonglong2 wa = *(const ulonglong2*)(sW + k * D + lane * 4);
        ulonglong2 wb = *(const ulonglong2*)(sW + (k + 1) * D + lane * 4);
#pragma unroll
        for (int j = 0; j < 8; j++) {
            float2 x2 = *(const float2*)(sX + (lr0 + j) * D + k);
            u64 xx0 = dup2(x2.x), xx1 = dup2(x2.y);
            ffma2(acc0[j], xx0, wa.x); ffma2(acc1[j], xx0, wa.y);
            ffma2(acc0[j], xx1, wb.x); ffma2(acc1[j], xx1, wb.y);
        }
    }
}

// epilogue: +bias, leaky-relu, return 4 values + per-lane sumsq contribution
__device__ __forceinline__ float epi4(u64 a0, u64 a1, float4 b4, float4& v) {
    float2 p01 = unpk(a0), p23 = unpk(a1);
    float t0 = p01.x + b4.x, t1 = p01.y + b4.y;
    float t2 = p23.x + b4.z, t3 = p23.y + b4.w;
    t0 = t0 > 0.f ? t0 : 0.2f * t0;
    t1 = t1 > 0.f ? t1 : 0.2f * t1;
    t2 = t2 > 0.f ? t2 : 0.2f * t2;
    t3 = t3 > 0.f ? t3 : 0.2f * t3;
    v = make_float4(t0, t1, t2, t3);
    return t0 * t0 + t1 * t1 + t2 * t2 + t3 * t3;
}

// ---------------- dense SAGE layer 1 (all users) ----------------
__global__ __launch_bounds__(256, 1) void k_dense1(
    const float* __restrict__ feat, const float* __restrict__ Ws,
    const float* __restrict__ Wn, const float* __restrict__ bias)
{
    extern __shared__ float sm[];
    float* sWs = sm;                    // 16384
    float* sWn = sm + 16384;            // 16384
    float* sB  = sm + 32768;            // 128
    float* sX  = sm + 32896;            // 64*128
    float* sH  = sm + 32896 + 64 * D;   // 64*128
    const int tid = threadIdx.x;
    {
        const float4* g0 = (const float4*)Ws;
        const float4* g1 = (const float4*)Wn;
        float4* s0 = (float4*)sWs;
        float4* s1 = (float4*)sWn;
        for (int i = tid; i < 4096; i += 256) { s0[i] = g0[i]; s1[i] = g1[i]; }
        if (tid < 32) ((float4*)sB)[tid] = ((const float4*)bias)[tid];
    }
    const int warp = tid >> 5, lane = tid & 31;
    const int lr0 = warp * 8;
    const int r0 = blockIdx.x * 64;
#pragma unroll
    for (int j = 0; j < 8; j++) {
        int row = r0 + lr0 + j;
        if (row < NU) {
            ((float4*)(sX + (lr0 + j) * D))[lane] =
                ((const float4*)(feat + (size_t)row * D))[lane];
            ((float4*)(sH + (lr0 + j) * D))[lane] =
                ((const float4*)(g_hn + (size_t)row * D))[lane];
        } else {
            ((float4*)(sX + (lr0 + j) * D))[lane] = make_float4(0.f, 0.f, 0.f, 0.f);
            ((float4*)(sH + (lr0 + j) * D))[lane] = make_float4(0.f, 0.f, 0.f, 0.f);
        }
    }
    __syncthreads();

    u64 acc0[8], acc1[8];
    gemm_dual8(sX, sH, sWs, sWn, lr0, lane, acc0, acc1);

    float4 b4 = ((const float4*)sB)[lane];
    float4 v[8]; float ss[8];
#pragma unroll
    for (int j = 0; j < 8; j++) ss[j] = epi4(acc0[j], acc1[j], b4, v[j]);
#pragma unroll
    for (int off = 16; off; off >>= 1) {
#pragma unroll
        for (int j = 0; j < 8; j++) ss[j] += __shfl_xor_sync(0xffffffffu, ss[j], off);
    }
#pragma unroll
    for (int j = 0; j < 8; j++) {
        int row = r0 + lr0 + j;
        if (row < NU) {
            float sc = 1.f / fmaxf(sqrtf(ss[j]), 1e-12f);
            ((float4*)(g_h1 + (size_t)row * D))[lane] =
                make_float4(v[j].x * sc, v[j].y * sc, v[j].z * sc, v[j].w * sc);
        }
    }
}

// ---------------- dense SAGE layer 2 (selected users only) ----------------
__global__ __launch_bounds__(256, 1) void k_dense2(
    const float* __restrict__ ufeat, const int* __restrict__ users,
    const float* __restrict__ Ws, const float* __restrict__ Wn,
    const float* __restrict__ bias, float* __restrict__ out)
{
    extern __shared__ float sm[];
    float* sWs = sm;
    float* sWn = sm + 16384;
    float* sB  = sm + 32768;
    float* sX  = sm + 32896;
    float* sH  = sm + 32896 + 64 * D;
    const int tid = threadIdx.x;
    {
        const float4* g0 = (const float4*)Ws;
        const float4* g1 = (const float4*)Wn;
        float4* s0 = (float4*)sWs;
        float4* s1 = (float4*)sWn;
        for (int i = tid; i < 4096; i += 256) { s0[i] = g0[i]; s1[i] = g1[i]; }
        if (tid < 32) ((float4*)sB)[tid] = ((const float4*)bias)[tid];
    }
    const int warp = tid >> 5, lane = tid & 31;
    const int lr0 = warp * 8;
    const int r0 = blockIdx.x * 64;     // NB % 64 == 0
#pragma unroll
    for (int j = 0; j < 8; j++) {
        int b = r0 + lr0 + j;
        int u = users[b];
        float4 x4 = ((const float4*)(g_h1 + (size_t)u * D))[lane];
        ((float4*)(sX + (lr0 + j) * D))[lane] = x4;
        ((float4*)(sH + (lr0 + j) * D))[lane] =
            ((const float4*)(g_hn2 + (size_t)b * D))[lane];
        ((float4*)(out + (size_t)b * 384))[lane]       = ((const float4*)(ufeat + (size_t)u * D))[lane];
        ((float4*)(out + (size_t)b * 384 + 128))[lane] = x4;
    }
    __syncthreads();

    u64 acc0[8], acc1[8];
    gemm_dual8(sX, sH, sWs, sWn, lr0, lane, acc0, acc1);

    float4 b4 = ((const float4*)sB)[lane];
    float4 v[8]; float ss[8];
#pragma unroll
    for (int j = 0; j < 8; j++) ss[j] = epi4(acc0[j], acc1[j], b4, v[j]);
#pragma unroll
    for (int off = 16; off; off >>= 1) {
#pragma unroll
        for (int j = 0; j < 8; j++) ss[j] += __shfl_xor_sync(0xffffffffu, ss[j], off);
    }
#pragma unroll
    for (int j = 0; j < 8; j++) {
        float sc = 1.f / fmaxf(sqrtf(ss[j]), 1e-12f);
        int b = r0 + lr0 + j;
        ((float4*)(out + (size_t)b * 384 + 256))[lane] =
            make_float4(v[j].x * sc, v[j].y * sc, v[j].z * sc, v[j].w * sc);
    }
}

// ---------------- item tower (gathered rows only) ----------------
__global__ __launch_bounds__(256, 1) void k_items(
    const float* __restrict__ ifeat, const int* __restrict__ pos, const int* __restrict__ neg,
    const float* __restrict__ W0, const float* __restrict__ b0,
    const float* __restrict__ W1, const float* __restrict__ b1,
    float* __restrict__ out)
{
    extern __shared__ float sm[];
    float* sW0 = sm;            // 16384
    float* sW1 = sm + 16384;    // 16384
    float* sB0 = sm + 32768;    // 128
    float* sB1 = sm + 32896;    // 128
    float* sX  = sm + 33024;    // 64*128
    const int tid = threadIdx.x;
    {
        const float4* g0 = (const float4*)W0;
        const float4* g1 = (const float4*)W1;
        float4* s0 = (float4*)sW0;
        float4* s1 = (float4*)sW1;
        for (int i = tid; i < 4096; i += 256) { s0[i] = g0[i]; s1[i] = g1[i]; }
        if (tid < 32) {
            ((float4*)sB0)[tid] = ((const float4*)b0)[tid];
            ((float4*)sB1)[tid] = ((const float4*)b1)[tid];
        }
    }
    const int warp = tid >> 5, lane = tid & 31;
    const int lr0 = warp * 8;
    const int r0 = blockIdx.x * 64;     // 2*NB % 64 == 0
#pragma unroll
    for (int j = 0; j < 8; j++) {
        int rr = r0 + lr0 + j;
        int idx = (rr < NB) ? pos[rr] : neg[rr - NB];
        float4 x4 = ((const float4*)(ifeat + (size_t)idx * D))[lane];
        ((float4*)(sX + (lr0 + j) * D))[lane] = x4;
        ((float4*)(out + (size_t)(NB + rr) * 384))[lane] = x4;   // raw feat segment
    }
    __syncthreads();

    // ---- layer 1 ----
    u64 acc0[8], acc1[8];
    gemm_one8(sX, sW0, lr0, lane, acc0, acc1);
    {
        float4 b4 = ((const float4*)sB0)[lane];
        float4 v[8]; float ss[8];
#pragma unroll
        for (int j = 0; j < 8; j++) ss[j] = epi4(acc0[j], acc1[j], b4, v[j]);
#pragma unroll
        for (int off = 16; off; off >>= 1) {
#pragma unroll
            for (int j = 0; j < 8; j++) ss[j] += __shfl_xor_sync(0xffffffffu, ss[j], off);
        }
        __syncwarp();   // all lanes done reading sX before overwrite
#pragma unroll
        for (int j = 0; j < 8; j++) {
            float sc = 1.f / fmaxf(sqrtf(ss[j]), 1e-12f);
            float4 o = make_float4(v[j].x * sc, v[j].y * sc, v[j].z * sc, v[j].w * sc);
            int rr = r0 + lr0 + j;
            ((float4*)(sX + (lr0 + j) * D))[lane] = o;    // becomes layer-2 input
            ((float4*)(out + (size_t)(NB + rr) * 384 + 128))[lane] = o;
        }
        __syncwarp();
    }

    // ---- layer 2 ----
    gemm_one8(sX, sW1, lr0, lane, acc0, acc1);
    {
        float4 b4 = ((const float4*)sB1)[lane];
        float4 v[8]; float ss[8];
#pragma unroll
        for (int j = 0; j < 8; j++) ss[j] = epi4(acc0[j], acc1[j], b4, v[j]);
#pragma unroll
        for (int off = 16; off; off >>= 1) {
#pragma unroll
            for (int j = 0; j < 8; j++) ss[j] += __shfl_xor_sync(0xffffffffu, ss[j], off);
        }
#pragma unroll
        for (int j = 0; j < 8; j++) {
            float sc = 1.f / fmaxf(sqrtf(ss[j]), 1e-12f);
            int rr = r0 + lr0 + j;
            ((float4*)(out + (size_t)(NB + rr) * 384 + 256))[lane] =
                make_float4(v[j].x * sc, v[j].y * sc, v[j].z * sc, v[j].w * sc);
        }
    }
}

// ---------------- launch ----------------
extern "C" void kernel_launch(void* const* d_in, const int* in_sizes, int n_in,
                              void* d_out, int out_size) {
    const int*   src   = (const int*)d_in[0];
    const int*   dst   = (const int*)d_in[1];
    const int*   users = (const int*)d_in[2];
    const int*   pos   = (const int*)d_in[3];
    const int*   neg   = (const int*)d_in[4];
    const float* ufeat = (const float*)d_in[5];
    const float* ifeat = (const float*)d_in[6];
    const float* Ws0   = (const float*)d_in[7];
    const float* Wn0   = (const float*)d_in[8];
    const float* bu0   = (const float*)d_in[9];
    const float* Wi0   = (const float*)d_in[10];
    const float* bi0   = (const float*)d_in[11];
    const float* Ws1   = (const float*)d_in[12];
    const float* Wn1   = (const float*)d_in[13];
    const float* bu1   = (const float*)d_in[14];
    const float* Wi1   = (const float*)d_in[15];
    const float* bi1   = (const float*)d_in[16];
    float* out = (float*)d_out;

    const int sm_dense = (16384 * 2 + 128 + 64 * D * 2) * sizeof(float);  // 197120 B
    const int sm_items = (16384 * 2 + 256 + 64 * D) * sizeof(float);      // 165888 B
    (void)cudaFuncSetAttribute(k_dense1, cudaFuncAttributeMaxDynamicSharedMemorySize, sm_dense);
    (void)cudaFuncSetAttribute(k_dense2, cudaFuncAttributeMaxDynamicSharedMemorySize, sm_dense);
    (void)cudaFuncSetAttribute(k_items,  cudaFuncAttributeMaxDynamicSharedMemorySize, sm_items);

    // item tower first (independent of the graph) — also overlaps CSR latency
    k_items <<<(2 * NB) / 64, 256, sm_items>>>(ifeat, pos, neg, Wi0, bi0, Wi1, bi1, out);

    // CSR build
    k_zero   <<<(NU + 255) / 256, 256>>>();
    k_count  <<<(NE / 8 + 255) / 256, 256>>>(dst);
    k_scan   <<<1, 1024>>>();
    k_scatter<<<(NE / 8 + 255) / 256, 256>>>(src, dst);

    // user tower: high-occupancy agg, then FFMA2 dense
    k_agg1  <<<(NU * 32 + 255) / 256, 256>>>(ufeat);
    k_dense1<<<(NU + 63) / 64, 256, sm_dense>>>(ufeat, Ws0, Wn0, bu0);
    k_agg2  <<<(NB * 32) / 256, 256>>>(users);
    k_dense2<<<NB / 64, 256, sm_dense>>>(ufeat, users, Ws1, Wn1, bu1, out);
}

// round 6
// speedup vs baseline: 1.8319x; 1.3004x over previous
#include <cuda_runtime.h>

#define NU 100000
#define NE 1600000
#define NB 16384
#define D  128
#define SCAN_B 98   // ceil(NU / 1024)

typedef unsigned long long u64;

// ---- static scratch (no allocations allowed) ----
static __device__ int   g_rowptr[NU + 1];
static __device__ int   g_cursor[NU];
static __device__ int   g_esrc[NE];
static __device__ int   g_bsum[SCAN_B];
static __device__ int   g_boff[SCAN_B];
static __device__ float g_h1 [(size_t)NU * D];   // layer-1 user output
static __device__ float g_hn [(size_t)NU * D];   // layer-1 neighbor mean
static __device__ float g_hn2[(size_t)NB * D];   // layer-2 neighbor mean

// ---------------- packed f32x2 helpers ----------------
__device__ __forceinline__ u64 dup2(float x) {
    u64 r; asm("mov.b64 %0, {%1, %1};" : "=l"(r) : "f"(x)); return r;
}
__device__ __forceinline__ void ffma2(u64& d, u64 a, u64 b) {
    asm("fma.rn.f32x2 %0, %1, %2, %0;" : "+l"(d) : "l"(a), "l"(b));
}
__device__ __forceinline__ float2 unpk(u64 v) {
    float2 r; asm("mov.b64 {%0, %1}, %2;" : "=f"(r.x), "=f"(r.y) : "l"(v)); return r;
}

// ---------------- CSR build ----------------
__global__ void k_zero() {
    int i = blockIdx.x * blockDim.x + threadIdx.x;
    if (i < NU) g_cursor[i] = 0;
}

__global__ void k_count(const int* __restrict__ dst) {
    int i = blockIdx.x * blockDim.x + threadIdx.x;   // NE/8 threads
    if (i < NE / 8) {
        int4 d0 = ((const int4*)dst)[2 * i];
        int4 d1 = ((const int4*)dst)[2 * i + 1];
        atomicAdd(&g_cursor[d0.x], 1); atomicAdd(&g_cursor[d0.y], 1);
        atomicAdd(&g_cursor[d0.z], 1); atomicAdd(&g_cursor[d0.w], 1);
        atomicAdd(&g_cursor[d1.x], 1); atomicAdd(&g_cursor[d1.y], 1);
        atomicAdd(&g_cursor[d1.z], 1); atomicAdd(&g_cursor[d1.w], 1);
    }
}

// ---- device-wide exclusive scan over g_cursor (3 kernels) ----
__global__ __launch_bounds__(1024) void k_scan_local() {
    __shared__ int sh[1024];
    const int t = threadIdx.x;
    const int i = blockIdx.x * 1024 + t;
    int c = (i < NU) ? g_cursor[i] : 0;
    int val = c;
    sh[t] = val;
    __syncthreads();
#pragma unroll
    for (int off = 1; off < 1024; off <<= 1) {
        int tmp = (t >= off) ? sh[t - off] : 0;
        __syncthreads();
        val += tmp;
        sh[t] = val;
        __syncthreads();
    }
    if (i < NU) g_rowptr[i] = val - c;       // block-local exclusive prefix
    if (t == 1023) g_bsum[blockIdx.x] = val; // block total
}

__global__ __launch_bounds__(128) void k_scan_top() {
    __shared__ int sh[128];
    const int t = threadIdx.x;
    int v = (t < SCAN_B) ? g_bsum[t] : 0;
    int val = v;
    sh[t] = val;
    __syncthreads();
#pragma unroll
    for (int off = 1; off < 128; off <<= 1) {
        int tmp = (t >= off) ? sh[t - off] : 0;
        __syncthreads();
        val += tmp;
        sh[t] = val;
        __syncthreads();
    }
    if (t < SCAN_B) g_boff[t] = val - v;     // exclusive block offsets
}

__global__ void k_scan_add() {
    int i = blockIdx.x * blockDim.x + threadIdx.x;
    if (i < NU) {
        int r = g_rowptr[i] + g_boff[i >> 10];
        g_rowptr[i] = r;
        g_cursor[i] = r;
    }
    if (i == 0) g_rowptr[NU] = NE;
}

__global__ void k_scatter(const int* __restrict__ src, const int* __restrict__ dst) {
    int i = blockIdx.x * blockDim.x + threadIdx.x;
    if (i < NE / 8) {
        int4 d0 = ((const int4*)dst)[2 * i];
        int4 d1 = ((const int4*)dst)[2 * i + 1];
        int4 s0 = ((const int4*)src)[2 * i];
        int4 s1 = ((const int4*)src)[2 * i + 1];
        int p0 = atomicAdd(&g_cursor[d0.x], 1);
        int p1 = atomicAdd(&g_cursor[d0.y], 1);
        int p2 = atomicAdd(&g_cursor[d0.z], 1);
        int p3 = atomicAdd(&g_cursor[d0.w], 1);
        int p4 = atomicAdd(&g_cursor[d1.x], 1);
        int p5 = atomicAdd(&g_cursor[d1.y], 1);
        int p6 = atomicAdd(&g_cursor[d1.z], 1);
        int p7 = atomicAdd(&g_cursor[d1.w], 1);
        g_esrc[p0] = s0.x; g_esrc[p1] = s0.y; g_esrc[p2] = s0.z; g_esrc[p3] = s0.w;
        g_esrc[p4] = s1.x; g_esrc[p5] = s1.y; g_esrc[p6] = s1.z; g_esrc[p7] = s1.w;
    }
}

// ---------------- high-occupancy neighbor-mean aggregation ----------------
__device__ __forceinline__ void agg_row(
    const float* __restrict__ table, int row, int lane, float* __restrict__ dstv)
{
    int beg = g_rowptr[row], end = g_rowptr[row + 1];
    int deg = end - beg;
    float4 a = make_float4(0.f, 0.f, 0.f, 0.f);
    for (int base = 0; base < deg; base += 32) {
        int rem = deg - base;
        int n = rem < 32 ? rem : 32;
        int myi = (lane < n) ? g_esrc[beg + base + lane] : 0;
        int j = 0;
        for (; j + 8 <= n; j += 8) {
            int s0 = __shfl_sync(0xffffffffu, myi, j + 0);
            int s1 = __shfl_sync(0xffffffffu, myi, j + 1);
            int s2 = __shfl_sync(0xffffffffu, myi, j + 2);
            int s3 = __shfl_sync(0xffffffffu, myi, j + 3);
            int s4 = __shfl_sync(0xffffffffu, myi, j + 4);
            int s5 = __shfl_sync(0xffffffffu, myi, j + 5);
            int s6 = __shfl_sync(0xffffffffu, myi, j + 6);
            int s7 = __shfl_sync(0xffffffffu, myi, j + 7);
            float4 x0 = ((const float4*)(table + (size_t)s0 * D))[lane];
            float4 x1 = ((const float4*)(table + (size_t)s1 * D))[lane];
            float4 x2 = ((const float4*)(table + (size_t)s2 * D))[lane];
            float4 x3 = ((const float4*)(table + (size_t)s3 * D))[lane];
            float4 x4 = ((const float4*)(table + (size_t)s4 * D))[lane];
            float4 x5 = ((const float4*)(table + (size_t)s5 * D))[lane];
            float4 x6 = ((const float4*)(table + (size_t)s6 * D))[lane];
            float4 x7 = ((const float4*)(table + (size_t)s7 * D))[lane];
            a.x += ((x0.x + x1.x) + (x2.x + x3.x)) + ((x4.x + x5.x) + (x6.x + x7.x));
            a.y += ((x0.y + x1.y) + (x2.y + x3.y)) + ((x4.y + x5.y) + (x6.y + x7.y));
            a.z += ((x0.z + x1.z) + (x2.z + x3.z)) + ((x4.z + x5.z) + (x6.z + x7.z));
            a.w += ((x0.w + x1.w) + (x2.w + x3.w)) + ((x4.w + x5.w) + (x6.w + x7.w));
        }
        for (; j < n; j++) {
            int s = __shfl_sync(0xffffffffu, myi, j);
            float4 x = ((const float4*)(table + (size_t)s * D))[lane];
            a.x += x.x; a.y += x.y; a.z += x.z; a.w += x.w;
        }
    }
    float inv = 1.f / fmaxf((float)deg, 1.f);
    a.x *= inv; a.y *= inv; a.z *= inv; a.w *= inv;
    ((float4*)dstv)[lane] = a;
}

__global__ __launch_bounds__(256) void k_agg1(const float* __restrict__ feat) {
    int row  = (blockIdx.x * blockDim.x + threadIdx.x) >> 5;
    int lane = threadIdx.x & 31;
    if (row < NU) agg_row(feat, row, lane, g_hn + (size_t)row * D);
}

__global__ __launch_bounds__(256) void k_agg2(const int* __restrict__ users) {
    int b    = (blockIdx.x * blockDim.x + threadIdx.x) >> 5;
    int lane = threadIdx.x & 31;
    if (b < NB) agg_row(g_h1, users[b], lane, g_hn2 + (size_t)b * D);
}

// ---------------- FFMA2 GEMM cores ----------------
__device__ __forceinline__ void gemm_dual8(
    const float* sX, const float* sH, const float* sWs, const float* sWn,
    int lr0, int lane, u64* acc0, u64* acc1)
{
#pragma unroll
    for (int j = 0; j < 8; j++) { acc0[j] = 0ull; acc1[j] = 0ull; }
#pragma unroll 4
    for (int k = 0; k < D; k += 2) {
        ulonglong2 wsa = *(const ulonglong2*)(sWs + k * D + lane * 4);
        ulonglong2 wsb = *(const ulonglong2*)(sWs + (k + 1) * D + lane * 4);
        ulonglong2 wna = *(const ulonglong2*)(sWn + k * D + lane * 4);
        ulonglong2 wnb = *(const ulonglong2*)(sWn + (k + 1) * D + lane * 4);
#pragma unroll
        for (int j = 0; j < 8; j++) {
            float2 x2 = *(const float2*)(sX + (lr0 + j) * D + k);
            float2 h2 = *(const float2*)(sH + (lr0 + j) * D + k);
            u64 xx0 = dup2(x2.x), xx1 = dup2(x2.y);
            u64 hh0 = dup2(h2.x), hh1 = dup2(h2.y);
            ffma2(acc0[j], xx0, wsa.x); ffma2(acc1[j], xx0, wsa.y);
            ffma2(acc0[j], hh0, wna.x); ffma2(acc1[j], hh0, wna.y);
            ffma2(acc0[j], xx1, wsb.x); ffma2(acc1[j], xx1, wsb.y);
            ffma2(acc0[j], hh1, wnb.x); ffma2(acc1[j], hh1, wnb.y);
        }
    }
}

__device__ __forceinline__ void gemm_one8(
    const float* sX, const float* sW, int lr0, int lane, u64* acc0, u64* acc1)
{
#pragma unroll
    for (int j = 0; j < 8; j++) { acc0[j] = 0ull; acc1[j] = 0ull; }
#pragma unroll 4
    for (int k = 0; k < D; k += 2) {
        ulonglong2 wa = *(const ulonglong2*)(sW + k * D + lane * 4);
        ulonglong2 wb = *(const ulonglong2*)(sW + (k + 1) * D + lane * 4);
#pragma unroll
        for (int j = 0; j < 8; j++) {
            float2 x2 = *(const float2*)(sX + (lr0 + j) * D + k);
            u64 xx0 = dup2(x2.x), xx1 = dup2(x2.y);
            ffma2(acc0[j], xx0, wa.x); ffma2(acc1[j], xx0, wa.y);
            ffma2(acc0[j], xx1, wb.x); ffma2(acc1[j], xx1, wb.y);
        }
    }
}

__device__ __forceinline__ float epi4(u64 a0, u64 a1, float4 b4, float4& v) {
    float2 p01 = unpk(a0), p23 = unpk(a1);
    float t0 = p01.x + b4.x, t1 = p01.y + b4.y;
    float t2 = p23.x + b4.z, t3 = p23.y + b4.w;
    t0 = t0 > 0.f ? t0 : 0.2f * t0;
    t1 = t1 > 0.f ? t1 : 0.2f * t1;
    t2 = t2 > 0.f ? t2 : 0.2f * t2;
    t3 = t3 > 0.f ? t3 : 0.2f * t3;
    v = make_float4(t0, t1, t2, t3);
    return t0 * t0 + t1 * t1 + t2 * t2 + t3 * t3;
}

// ---------------- dense SAGE layer 1 (all users) ----------------
__global__ __launch_bounds__(256, 1) void k_dense1(
    const float* __restrict__ feat, const float* __restrict__ Ws,
    const float* __restrict__ Wn, const float* __restrict__ bias)
{
    extern __shared__ float sm[];
    float* sWs = sm;                    // 16384
    float* sWn = sm + 16384;            // 16384
    float* sB  = sm + 32768;            // 128
    float* sX  = sm + 32896;            // 64*128
    float* sH  = sm + 32896 + 64 * D;   // 64*128
    const int tid = threadIdx.x;
    {
        const float4* g0 = (const float4*)Ws;
        const float4* g1 = (const float4*)Wn;
        float4* s0 = (float4*)sWs;
        float4* s1 = (float4*)sWn;
        for (int i = tid; i < 4096; i += 256) { s0[i] = g0[i]; s1[i] = g1[i]; }
        if (tid < 32) ((float4*)sB)[tid] = ((const float4*)bias)[tid];
    }
    const int warp = tid >> 5, lane = tid & 31;
    const int lr0 = warp * 8;
    const int r0 = blockIdx.x * 64;
#pragma unroll
    for (int j = 0; j < 8; j++) {
        int row = r0 + lr0 + j;
        if (row < NU) {
            ((float4*)(sX + (lr0 + j) * D))[lane] =
                ((const float4*)(feat + (size_t)row * D))[lane];
            ((float4*)(sH + (lr0 + j) * D))[lane] =
                ((const float4*)(g_hn + (size_t)row * D))[lane];
        } else {
            ((float4*)(sX + (lr0 + j) * D))[lane] = make_float4(0.f, 0.f, 0.f, 0.f);
            ((float4*)(sH + (lr0 + j) * D))[lane] = make_float4(0.f, 0.f, 0.f, 0.f);
        }
    }
    __syncthreads();

    u64 acc0[8], acc1[8];
    gemm_dual8(sX, sH, sWs, sWn, lr0, lane, acc0, acc1);

    float4 b4 = ((const float4*)sB)[lane];
    float4 v[8]; float ss[8];
#pragma unroll
    for (int j = 0; j < 8; j++) ss[j] = epi4(acc0[j], acc1[j], b4, v[j]);
#pragma unroll
    for (int off = 16; off; off >>= 1) {
#pragma unroll
        for (int j = 0; j < 8; j++) ss[j] += __shfl_xor_sync(0xffffffffu, ss[j], off);
    }
#pragma unroll
    for (int j = 0; j < 8; j++) {
        int row = r0 + lr0 + j;
        if (row < NU) {
            float sc = 1.f / fmaxf(sqrtf(ss[j]), 1e-12f);
            ((float4*)(g_h1 + (size_t)row * D))[lane] =
                make_float4(v[j].x * sc, v[j].y * sc, v[j].z * sc, v[j].w * sc);
        }
    }
}

// ---------------- dense SAGE layer 2 (selected users only) ----------------
__global__ __launch_bounds__(256, 1) void k_dense2(
    const float* __restrict__ ufeat, const int* __restrict__ users,
    const float* __restrict__ Ws, const float* __restrict__ Wn,
    const float* __restrict__ bias, float* __restrict__ out)
{
    extern __shared__ float sm[];
    float* sWs = sm;
    float* sWn = sm + 16384;
    float* sB  = sm + 32768;
    float* sX  = sm + 32896;
    float* sH  = sm + 32896 + 64 * D;
    const int tid = threadIdx.x;
    {
        const float4* g0 = (const float4*)Ws;
        const float4* g1 = (const float4*)Wn;
        float4* s0 = (float4*)sWs;
        float4* s1 = (float4*)sWn;
        for (int i = tid; i < 4096; i += 256) { s0[i] = g0[i]; s1[i] = g1[i]; }
        if (tid < 32) ((float4*)sB)[tid] = ((const float4*)bias)[tid];
    }
    const int warp = tid >> 5, lane = tid & 31;
    const int lr0 = warp * 8;
    const int r0 = blockIdx.x * 64;     // NB % 64 == 0
#pragma unroll
    for (int j = 0; j < 8; j++) {
        int b = r0 + lr0 + j;
        int u = users[b];
        float4 x4 = ((const float4*)(g_h1 + (size_t)u * D))[lane];
        ((float4*)(sX + (lr0 + j) * D))[lane] = x4;
        ((float4*)(sH + (lr0 + j) * D))[lane] =
            ((const float4*)(g_hn2 + (size_t)b * D))[lane];
        ((float4*)(out + (size_t)b * 384))[lane]       = ((const float4*)(ufeat + (size_t)u * D))[lane];
        ((float4*)(out + (size_t)b * 384 + 128))[lane] = x4;
    }
    __syncthreads();

    u64 acc0[8], acc1[8];
    gemm_dual8(sX, sH, sWs, sWn, lr0, lane, acc0, acc1);

    float4 b4 = ((const float4*)sB)[lane];
    float4 v[8]; float ss[8];
#pragma unroll
    for (int j = 0; j < 8; j++) ss[j] = epi4(acc0[j], acc1[j], b4, v[j]);
#pragma unroll
    for (int off = 16; off; off >>= 1) {
#pragma unroll
        for (int j = 0; j < 8; j++) ss[j] += __shfl_xor_sync(0xffffffffu, ss[j], off);
    }
#pragma unroll
    for (int j = 0; j < 8; j++) {
        float sc = 1.f / fmaxf(sqrtf(ss[j]), 1e-12f);
        int b = r0 + lr0 + j;
        ((float4*)(out + (size_t)b * 384 + 256))[lane] =
            make_float4(v[j].x * sc, v[j].y * sc, v[j].z * sc, v[j].w * sc);
    }
}

// ---------------- item tower (gathered rows only) ----------------
__global__ __launch_bounds__(256, 1) void k_items(
    const float* __restrict__ ifeat, const int* __restrict__ pos, const int* __restrict__ neg,
    const float* __restrict__ W0, const float* __restrict__ b0,
    const float* __restrict__ W1, const float* __restrict__ b1,
    float* __restrict__ out)
{
    extern __shared__ float sm[];
    float* sW0 = sm;            // 16384
    float* sW1 = sm + 16384;    // 16384
    float* sB0 = sm + 32768;    // 128
    float* sB1 = sm + 32896;    // 128
    float* sX  = sm + 33024;    // 64*128
    const int tid = threadIdx.x;
    {
        const float4* g0 = (const float4*)W0;
        const float4* g1 = (const float4*)W1;
        float4* s0 = (float4*)sW0;
        float4* s1 = (float4*)sW1;
        for (int i = tid; i < 4096; i += 256) { s0[i] = g0[i]; s1[i] = g1[i]; }
        if (tid < 32) {
            ((float4*)sB0)[tid] = ((const float4*)b0)[tid];
            ((float4*)sB1)[tid] = ((const float4*)b1)[tid];
        }
    }
    const int warp = tid >> 5, lane = tid & 31;
    const int lr0 = warp * 8;
    const int r0 = blockIdx.x * 64;     // 2*NB % 64 == 0
#pragma unroll
    for (int j = 0; j < 8; j++) {
        int rr = r0 + lr0 + j;
        int idx = (rr < NB) ? pos[rr] : neg[rr - NB];
        float4 x4 = ((const float4*)(ifeat + (size_t)idx * D))[lane];
        ((float4*)(sX + (lr0 + j) * D))[lane] = x4;
        ((float4*)(out + (size_t)(NB + rr) * 384))[lane] = x4;   // raw feat segment
    }
    __syncthreads();

    // ---- layer 1 ----
    u64 acc0[8], acc1[8];
    gemm_one8(sX, sW0, lr0, lane, acc0, acc1);
    {
        float4 b4 = ((const float4*)sB0)[lane];
        float4 v[8]; float ss[8];
#pragma unroll
        for (int j = 0; j < 8; j++) ss[j] = epi4(acc0[j], acc1[j], b4, v[j]);
#pragma unroll
        for (int off = 16; off; off >>= 1) {
#pragma unroll
            for (int j = 0; j < 8; j++) ss[j] += __shfl_xor_sync(0xffffffffu, ss[j], off);
        }
        __syncwarp();   // all lanes done reading sX before overwrite
#pragma unroll
        for (int j = 0; j < 8; j++) {
            float sc = 1.f / fmaxf(sqrtf(ss[j]), 1e-12f);
            float4 o = make_float4(v[j].x * sc, v[j].y * sc, v[j].z * sc, v[j].w * sc);
            int rr = r0 + lr0 + j;
            ((float4*)(sX + (lr0 + j) * D))[lane] = o;    // becomes layer-2 input
            ((float4*)(out + (size_t)(NB + rr) * 384 + 128))[lane] = o;
        }
        __syncwarp();
    }

    // ---- layer 2 ----
    gemm_one8(sX, sW1, lr0, lane, acc0, acc1);
    {
        float4 b4 = ((const float4*)sB1)[lane];
        float4 v[8]; float ss[8];
#pragma unroll
        for (int j = 0; j < 8; j++) ss[j] = epi4(acc0[j], acc1[j], b4, v[j]);
#pragma unroll
        for (int off = 16; off; off >>= 1) {
#pragma unroll
            for (int j = 0; j < 8; j++) ss[j] += __shfl_xor_sync(0xffffffffu, ss[j], off);
        }
#pragma unroll
        for (int j = 0; j < 8; j++) {
            float sc = 1.f / fmaxf(sqrtf(ss[j]), 1e-12f);
            int rr = r0 + lr0 + j;
            ((float4*)(out + (size_t)(NB + rr) * 384 + 256))[lane] =
                make_float4(v[j].x * sc, v[j].y * sc, v[j].z * sc, v[j].w * sc);
        }
    }
}

// ---------------- launch ----------------
extern "C" void kernel_launch(void* const* d_in, const int* in_sizes, int n_in,
                              void* d_out, int out_size) {
    const int*   src   = (const int*)d_in[0];
    const int*   dst   = (const int*)d_in[1];
    const int*   users = (const int*)d_in[2];
    const int*   pos   = (const int*)d_in[3];
    const int*   neg   = (const int*)d_in[4];
    const float* ufeat = (const float*)d_in[5];
    const float* ifeat = (const float*)d_in[6];
    const float* Ws0   = (const float*)d_in[7];
    const float* Wn0   = (const float*)d_in[8];
    const float* bu0   = (const float*)d_in[9];
    const float* Wi0   = (const float*)d_in[10];
    const float* bi0   = (const float*)d_in[11];
    const float* Ws1   = (const float*)d_in[12];
    const float* Wn1   = (const float*)d_in[13];
    const float* bu1   = (const float*)d_in[14];
    const float* Wi1   = (const float*)d_in[15];
    const float* bi1   = (const float*)d_in[16];
    float* out = (float*)d_out;

    const int sm_dense = (16384 * 2 + 128 + 64 * D * 2) * sizeof(float);  // 197120 B
    const int sm_items = (16384 * 2 + 256 + 64 * D) * sizeof(float);      // 165888 B
    (void)cudaFuncSetAttribute(k_dense1, cudaFuncAttributeMaxDynamicSharedMemorySize, sm_dense);
    (void)cudaFuncSetAttribute(k_dense2, cudaFuncAttributeMaxDynamicSharedMemorySize, sm_dense);
    (void)cudaFuncSetAttribute(k_items,  cudaFuncAttributeMaxDynamicSharedMemorySize, sm_items);

    // item tower first (independent of the graph)
    k_items <<<(2 * NB) / 64, 256, sm_items>>>(ifeat, pos, neg, Wi0, bi0, Wi1, bi1, out);

    // CSR build with device-wide parallel scan
    k_zero      <<<(NU + 255) / 256, 256>>>();
    k_count     <<<(NE / 8 + 255) / 256, 256>>>(dst);
    k_scan_local<<<SCAN_B, 1024>>>();
    k_scan_top  <<<1, 128>>>();
    k_scan_add  <<<(NU + 255) / 256, 256>>>();
    k_scatter   <<<(NE / 8 + 255) / 256, 256>>>(src, dst);

    // user tower: high-occupancy agg, then FFMA2 dense
    k_agg1  <<<(NU * 32 + 255) / 256, 256>>>(ufeat);
    k_dense1<<<(NU + 63) / 64, 256, sm_dense>>>(ufeat, Ws0, Wn0, bu0);
    k_agg2  <<<(NB * 32) / 256, 256>>>(users);
    k_dense2<<<NB / 64, 256, sm_dense>>>(ufeat, users, Ws1, Wn1, bu1, out);
}